// round 2
// baseline (speedup 1.0000x reference)
#include <cuda_runtime.h>
#include <math.h>

#define NROWS 19712   // 256*77
#define SEQ 77
#define BATCH 256
#define DIM 1024
#define EPSF 1e-15f
#define MAXNORM (1.0f - 1e-5f)

// scratch (no allocations allowed)
__device__ float g_bufA[(size_t)NROWS * DIM];
__device__ float g_bufB[(size_t)NROWS * DIM];
__device__ int g_tok64;

// ---------------------------------------------------------------------------
// Detect whether tokens buffer is int64 or int32 on the wire.
// Read first NROWS/2 u64 words (safe under both layouts). If any word has a
// nonzero high half, the layout must be int32 (two packed tokens).
// ---------------------------------------------------------------------------
__global__ void detect_tok_kernel(const unsigned long long* __restrict__ w, int nwords) {
    __shared__ int flag;
    if (threadIdx.x == 0) flag = 0;
    __syncthreads();
    int bad = 0;
    for (int i = threadIdx.x; i < nwords; i += blockDim.x) {
        if (w[i] >> 32) { bad = 1; break; }
    }
    if (bad) flag = 1;
    __syncthreads();
    if (threadIdx.x == 0) g_tok64 = flag ? 0 : 1;
}

// ---------------------------------------------------------------------------
// x[b,s,:] = tok_w[tokens[b,s]] + pos_w[s]
// ---------------------------------------------------------------------------
__global__ void embed_kernel(const void* __restrict__ tokens,
                             const float* __restrict__ tok_w,
                             const float* __restrict__ pos_w,
                             float* __restrict__ x) {
    int row = blockIdx.x;
    int s = row % SEQ;
    long long t;
    if (g_tok64) t = ((const long long*)tokens)[row];
    else         t = (long long)(((const int*)tokens)[row]);
    const float4* src = (const float4*)(tok_w + (size_t)t * DIM);
    const float4* pp  = (const float4*)(pos_w + (size_t)s * DIM);
    float4* dst = (float4*)(x + (size_t)row * DIM);
    int i = threadIdx.x;  // 256 threads * 4 floats = 1024
    float4 a = src[i];
    float4 p = pp[i];
    a.x += p.x; a.y += p.y; a.z += p.z; a.w += p.w;
    dst[i] = a;
}

// ---------------------------------------------------------------------------
// C = A @ W (+bias) (+SiLU).  A:[N,1024] W:[1024,1024] row-major.
// Tiles: BM=BN=128, BK=16, 256 threads, 8x8 per-thread microtile.
// N is a multiple of 128 (19712 = 154*128) -> no bounds checks.
// ---------------------------------------------------------------------------
#define BM 128
#define BN 128
#define BK 16
#define TM 8
#define TN 8

__global__ __launch_bounds__(256, 2) void sgemm_kernel(
    const float* __restrict__ A, const float* __restrict__ W,
    const float* __restrict__ bias, float* __restrict__ C, int applySilu)
{
    __shared__ float As[BK][BM + 4];   // transposed A tile, padded
    __shared__ float Bs[BK][BN];

    int tid = threadIdx.x;
    int bm = blockIdx.x * BM;
    int bn = blockIdx.y * BN;

    int tr = tid / 16, tc = tid % 16;
    int tm0 = tr * TM, tn0 = tc * TN;

    int arow  = tid / 4;       // 0..63
    int acol4 = tid % 4;       // float4 slot in 16-wide K slab
    int brow  = tid / 32;      // 0..7
    int bcol4 = tid % 32;      // float4 slot in 128-wide N slab

    float acc[TM][TN] = {};

    for (int k0 = 0; k0 < DIM; k0 += BK) {
        #pragma unroll
        for (int h = 0; h < 2; ++h) {
            int r = arow + h * 64;
            float4 v = *(const float4*)(A + (size_t)(bm + r) * DIM + k0 + acol4 * 4);
            As[acol4 * 4 + 0][r] = v.x;
            As[acol4 * 4 + 1][r] = v.y;
            As[acol4 * 4 + 2][r] = v.z;
            As[acol4 * 4 + 3][r] = v.w;
        }
        #pragma unroll
        for (int h = 0; h < 2; ++h) {
            int r = brow + h * 8;
            *(float4*)&Bs[r][bcol4 * 4] =
                *(const float4*)(W + (size_t)(k0 + r) * DIM + bn + bcol4 * 4);
        }
        __syncthreads();

        #pragma unroll
        for (int k = 0; k < BK; ++k) {
            float a[TM], b[TN];
            #pragma unroll
            for (int i = 0; i < TM; ++i) a[i] = As[k][tm0 + i];
            #pragma unroll
            for (int j = 0; j < TN; ++j) b[j] = Bs[k][tn0 + j];
            #pragma unroll
            for (int i = 0; i < TM; ++i)
                #pragma unroll
                for (int j = 0; j < TN; ++j)
                    acc[i][j] += a[i] * b[j];
        }
        __syncthreads();
    }

    #pragma unroll
    for (int i = 0; i < TM; ++i) {
        #pragma unroll
        for (int j = 0; j < TN; ++j) {
            float v = acc[i][j];
            if (bias) v += bias[bn + tn0 + j];
            if (applySilu) v = v / (1.0f + expf(-v));
            C[(size_t)(bm + tm0 + i) * DIM + bn + tn0 + j] = v;
        }
    }
}

// ---------------------------------------------------------------------------
// block reduction over 256 threads
// ---------------------------------------------------------------------------
__device__ __forceinline__ float block_reduce_sum_256(float v) {
    __shared__ float s[8];
    __syncthreads();
    int lane = threadIdx.x & 31, w = threadIdx.x >> 5;
    #pragma unroll
    for (int o = 16; o; o >>= 1) v += __shfl_down_sync(0xffffffffu, v, o);
    if (lane == 0) s[w] = v;
    __syncthreads();
    if (threadIdx.x == 0) {
        float t = 0.f;
        #pragma unroll
        for (int i = 0; i < 8; ++i) t += s[i];
        s[0] = t;
    }
    __syncthreads();
    return s[0];
}

// ---------------------------------------------------------------------------
// he = logmap0(expmap0(x)) : per-row scale atanh(min(tanh(|x|),M))/|x|
// one block per row (1024 elems, 256 threads x float4)
// ---------------------------------------------------------------------------
__global__ void he_kernel(const float* __restrict__ in, float* __restrict__ out) {
    size_t base = (size_t)blockIdx.x * DIM;
    float4 v = ((const float4*)(in + base))[threadIdx.x];
    float ss = v.x * v.x + v.y * v.y + v.z * v.z + v.w * v.w;
    float sum = block_reduce_sum_256(ss);
    float n = fmaxf(sqrtf(sum), EPSF);
    float sc = atanhf(fminf(tanhf(n), MAXNORM)) / n;
    v.x *= sc; v.y *= sc; v.z *= sc; v.w *= sc;
    ((float4*)(out + base))[threadIdx.x] = v;
}

// ---------------------------------------------------------------------------
// agg[b,c,d] = sum_r (edge[b,r,c]!=0) * m[b,r,d] + bias[d]; in-place over m.
// block = (b, d-chunk of 128), 128 threads (one per d).
// ---------------------------------------------------------------------------
__global__ __launch_bounds__(128) void agg_kernel(float* __restrict__ m,
                                                  const int* __restrict__ edge,
                                                  const float* __restrict__ bias) {
    __shared__ float msm[SEQ * 128];
    __shared__ unsigned char adj[SEQ * 80];

    int b = blockIdx.x;
    int d0 = blockIdx.y * 128;
    int tid = threadIdx.x;

    float* mb = m + (size_t)b * SEQ * DIM + d0;
    for (int r = 0; r < SEQ; ++r)
        msm[r * 128 + tid] = mb[(size_t)r * DIM + tid];

    const int* eb = edge + (size_t)b * SEQ * SEQ;
    for (int i = tid; i < SEQ * SEQ; i += 128)
        adj[(i / SEQ) * 80 + (i % SEQ)] = (unsigned char)(eb[i] != 0);
    __syncthreads();

    float bd = bias[d0 + tid];
    for (int c = 0; c < SEQ; ++c) {
        float acc = bd;
        #pragma unroll 7
        for (int r = 0; r < SEQ; ++r)
            acc += (float)adj[r * 80 + c] * msm[r * 128 + tid];
        mb[(size_t)c * DIM + tid] = acc;   // safe: all reads came from smem
    }
}

// ---------------------------------------------------------------------------
// out = logmap0(expmap0(leaky_relu(logmap0(expmap0(agg)))))
// ---------------------------------------------------------------------------
__global__ void final_kernel(const float* __restrict__ in, float* __restrict__ out) {
    size_t base = (size_t)blockIdx.x * DIM;
    float4 v = ((const float4*)(in + base))[threadIdx.x];
    float ss = v.x * v.x + v.y * v.y + v.z * v.z + v.w * v.w;
    float sum = block_reduce_sum_256(ss);
    float n1 = fmaxf(sqrtf(sum), EPSF);
    float sc1 = atanhf(fminf(tanhf(n1), MAXNORM)) / n1;

    float u0 = sc1 * v.x; u0 = (u0 > 0.f) ? u0 : 0.01f * u0;
    float u1 = sc1 * v.y; u1 = (u1 > 0.f) ? u1 : 0.01f * u1;
    float u2 = sc1 * v.z; u2 = (u2 > 0.f) ? u2 : 0.01f * u2;
    float u3 = sc1 * v.w; u3 = (u3 > 0.f) ? u3 : 0.01f * u3;

    float ss2 = u0 * u0 + u1 * u1 + u2 * u2 + u3 * u3;
    float sum2 = block_reduce_sum_256(ss2);
    float n2 = fmaxf(sqrtf(sum2), EPSF);
    float sc2 = atanhf(fminf(tanhf(n2), MAXNORM)) / n2;

    float4 o;
    o.x = sc2 * u0; o.y = sc2 * u1; o.z = sc2 * u2; o.w = sc2 * u3;
    ((float4*)(out + base))[threadIdx.x] = o;
}

// ---------------------------------------------------------------------------
extern "C" void kernel_launch(void* const* d_in, const int* in_sizes, int n_in,
                              void* d_out, int out_size) {
    const void*  tokens = d_in[0];
    const int*   edge   = (const int*)d_in[1];
    const float* tok_w  = (const float*)d_in[2];
    const float* pos_w  = (const float*)d_in[3];
    const float* mlp_w  = (const float*)d_in[4];
    const float* mlp_b  = (const float*)d_in[5];
    const float* gcn_w  = (const float*)d_in[6];
    const float* gcn_b  = (const float*)d_in[7];
    float* out = (float*)d_out;

    float *bufA, *bufB;
    cudaGetSymbolAddress((void**)&bufA, g_bufA);
    cudaGetSymbolAddress((void**)&bufB, g_bufB);

    detect_tok_kernel<<<1, 256>>>((const unsigned long long*)tokens, NROWS / 2);
    embed_kernel<<<NROWS, 256>>>(tokens, tok_w, pos_w, bufA);

    dim3 gg(NROWS / BM, DIM / BN);
    // project_emb: 5 linears, SiLU after first 4
    sgemm_kernel<<<gg, 256>>>(bufA, mlp_w + (size_t)0 * DIM * DIM, mlp_b + 0 * DIM, bufB, 1);
    sgemm_kernel<<<gg, 256>>>(bufB, mlp_w + (size_t)1 * DIM * DIM, mlp_b + 1 * DIM, bufA, 1);
    sgemm_kernel<<<gg, 256>>>(bufA, mlp_w + (size_t)2 * DIM * DIM, mlp_b + 2 * DIM, bufB, 1);
    sgemm_kernel<<<gg, 256>>>(bufB, mlp_w + (size_t)3 * DIM * DIM, mlp_b + 3 * DIM, bufA, 1);
    sgemm_kernel<<<gg, 256>>>(bufA, mlp_w + (size_t)4 * DIM * DIM, mlp_b + 4 * DIM, bufB, 0);

    // he = logmap0(expmap0(x))  (identical for all 4 GCN layers)
    he_kernel<<<NROWS, 256>>>(bufB, bufA);

    // Only GCN layer i=3 affects the output (h is recomputed from graph_node
    // every iteration in the reference; layers 0-2 are dead).
    sgemm_kernel<<<gg, 256>>>(bufA, gcn_w + (size_t)3 * DIM * DIM, (const float*)nullptr, bufB, 0);
    agg_kernel<<<dim3(BATCH, DIM / 128), 128>>>(bufB, edge, gcn_b + 3 * DIM);

    final_kernel<<<NROWS, 256>>>(bufB, out);
}

// round 4
// speedup vs baseline: 2.0683x; 2.0683x over previous
#include <cuda_runtime.h>
#include <cuda_bf16.h>
#include <math.h>
#include <stdint.h>

#define NROWS 19712   // 256*77
#define SEQ 77
#define BATCH 256
#define DIM 1024
#define EPSF 1e-15f
#define MAXNORM (1.0f - 1e-5f)

// scratch (no allocations allowed)
__device__ __nv_bfloat16 g_ahi[(size_t)NROWS * DIM];
__device__ __nv_bfloat16 g_alo[(size_t)NROWS * DIM];
__device__ __nv_bfloat16 g_bhi[(size_t)NROWS * DIM];
__device__ __nv_bfloat16 g_blo[(size_t)NROWS * DIM];
__device__ float g_bufF[(size_t)NROWS * DIM];
__device__ __nv_bfloat16 g_whi[(size_t)6 * DIM * DIM];  // transposed [N][K]
__device__ __nv_bfloat16 g_wlo[(size_t)6 * DIM * DIM];
__device__ int g_tok64;

// ===========================================================================
// PTX helpers (all baseline sm_80+ features, valid at compute_103)
// ===========================================================================
__device__ __forceinline__ uint32_t smem_u32(const void* p) {
    uint32_t a;
    asm("{ .reg .u64 t; cvta.to.shared.u64 t, %1; cvt.u32.u64 %0, t; }" : "=r"(a) : "l"(p));
    return a;
}
__device__ __forceinline__ void cp_async16(uint32_t dst, const void* src) {
    asm volatile("cp.async.cg.shared.global [%0], [%1], 16;" :: "r"(dst), "l"(src) : "memory");
}
__device__ __forceinline__ void cp_commit() {
    asm volatile("cp.async.commit_group;" ::: "memory");
}
#define CP_WAIT(n) asm volatile("cp.async.wait_group %0;" :: "n"(n) : "memory")

__device__ __forceinline__ void ldsm4(uint32_t addr, uint32_t& r0, uint32_t& r1,
                                      uint32_t& r2, uint32_t& r3) {
    asm volatile("ldmatrix.sync.aligned.m8n8.x4.shared.b16 {%0,%1,%2,%3}, [%4];"
                 : "=r"(r0), "=r"(r1), "=r"(r2), "=r"(r3) : "r"(addr));
}
__device__ __forceinline__ void mma_bf16(float& d0, float& d1, float& d2, float& d3,
                                         uint32_t a0, uint32_t a1, uint32_t a2, uint32_t a3,
                                         uint32_t b0, uint32_t b1) {
    asm volatile("mma.sync.aligned.m16n8k16.row.col.f32.bf16.bf16.f32 "
                 "{%0,%1,%2,%3},{%4,%5,%6,%7},{%8,%9},{%0,%1,%2,%3};"
                 : "+f"(d0), "+f"(d1), "+f"(d2), "+f"(d3)
                 : "r"(a0), "r"(a1), "r"(a2), "r"(a3), "r"(b0), "r"(b1));
}
__device__ __forceinline__ void split_bf16(float v, __nv_bfloat16& hi, __nv_bfloat16& lo) {
    hi = __float2bfloat16(v);
    lo = __float2bfloat16(v - __bfloat162float(hi));
}

// ===========================================================================
// Token layout detection (int64 vs int32 wire format)
// ===========================================================================
__global__ void detect_tok_kernel(const unsigned long long* __restrict__ w, int nwords) {
    __shared__ int flag;
    if (threadIdx.x == 0) flag = 0;
    __syncthreads();
    int bad = 0;
    for (int i = threadIdx.x; i < nwords; i += blockDim.x)
        if (w[i] >> 32) { bad = 1; break; }
    if (bad) flag = 1;
    __syncthreads();
    if (threadIdx.x == 0) g_tok64 = flag ? 0 : 1;
}

// ===========================================================================
// Embedding -> hi/lo bf16 split
// ===========================================================================
__global__ void embed_kernel(const void* __restrict__ tokens,
                             const float* __restrict__ tok_w,
                             const float* __restrict__ pos_w,
                             __nv_bfloat16* __restrict__ xhi,
                             __nv_bfloat16* __restrict__ xlo) {
    int row = blockIdx.x;
    int s = row % SEQ;
    long long t;
    if (g_tok64) t = ((const long long*)tokens)[row];
    else         t = (long long)(((const int*)tokens)[row]);
    int i = threadIdx.x;
    float4 a = ((const float4*)(tok_w + (size_t)t * DIM))[i];
    float4 p = ((const float4*)(pos_w + (size_t)s * DIM))[i];
    float v[4] = {a.x + p.x, a.y + p.y, a.z + p.z, a.w + p.w};
    __nv_bfloat16 h[4], l[4];
    #pragma unroll
    for (int q = 0; q < 4; ++q) split_bf16(v[q], h[q], l[q]);
    size_t base = (size_t)row * DIM + i * 4;
    *(uint2*)(xhi + base) = *(uint2*)h;
    *(uint2*)(xlo + base) = *(uint2*)l;
}

// ===========================================================================
// Weight transpose + split: whi/wlo[mat][n*DIM+k] = split(src[k*DIM+n])
// mats 0-4 = mlp_w[0..4], mat 5 = gcn_w[3]
// ===========================================================================
__global__ void wsplit_kernel(const float* __restrict__ mlp_w,
                              const float* __restrict__ gcn_w,
                              __nv_bfloat16* __restrict__ whi,
                              __nv_bfloat16* __restrict__ wlo) {
    __shared__ float t[32][33];
    int mat = blockIdx.z;
    const float* src = (mat < 5) ? mlp_w + (size_t)mat * DIM * DIM
                                 : gcn_w + (size_t)3 * DIM * DIM;
    size_t doff = (size_t)mat * DIM * DIM;
    int n0 = blockIdx.x * 32, k0 = blockIdx.y * 32;
    for (int i = threadIdx.y; i < 32; i += 8)
        t[i][threadIdx.x] = src[(size_t)(k0 + i) * DIM + n0 + threadIdx.x];
    __syncthreads();
    for (int i = threadIdx.y; i < 32; i += 8) {
        float v = t[threadIdx.x][i];   // element (n=n0+i, k=k0+tx)
        __nv_bfloat16 h, l;
        split_bf16(v, h, l);
        size_t d = doff + (size_t)(n0 + i) * DIM + k0 + threadIdx.x;
        whi[d] = h; wlo[d] = l;
    }
}

// ===========================================================================
// bf16 3-pass GEMM via mma.sync: C = A @ Wt^T (+bias)(+SiLU)
// A = Ahi + Alo, B = Bhi + Blo; accumulate Ah*Bh + Al*Bh + Ah*Bl in fp32.
// Tile 128x128, BK=32, 4-stage cp.async pipeline, 8 warps x (64x32).
// Output either fused-split (outHi/outLo) or fp32 (outF).
// ===========================================================================
#define STAGES 4
#define CHUNKS 96              // 3 phases x 32 chunks (K=1024, BK=32)
#define A_STRIDE 80            // 32 bf16 = 64B data + 16B pad
#define TILE_A_BYTES (128 * A_STRIDE)      // 10240
#define STAGE_BYTES  (2 * TILE_A_BYTES)    // 20480
#define DSM_BYTES (STAGES * STAGE_BYTES)   // 81920

__global__ __launch_bounds__(256, 2) void mma_gemm_kernel(
    const __nv_bfloat16* __restrict__ Ahi, const __nv_bfloat16* __restrict__ Alo,
    const __nv_bfloat16* __restrict__ Bhi, const __nv_bfloat16* __restrict__ Blo,
    const float* __restrict__ bias,
    __nv_bfloat16* __restrict__ outHi, __nv_bfloat16* __restrict__ outLo,
    float* __restrict__ outF, int applySilu)
{
    extern __shared__ char dsm_raw[];
    uint32_t dsm = smem_u32(dsm_raw);

    int tid = threadIdx.x, wid = tid >> 5, lid = tid & 31;
    int bm = blockIdx.x * 128, bn = blockIdx.y * 128;
    int wm = wid & 1, wn = wid >> 1;   // warp tile: rows wm*64, cols wn*32

    float acc[4][4][4];
    #pragma unroll
    for (int i = 0; i < 4; ++i)
        #pragma unroll
        for (int j = 0; j < 4; ++j)
            #pragma unroll
            for (int r = 0; r < 4; ++r) acc[i][j][r] = 0.f;

    // per-thread load indices: 512 16B-chunks per operand tile, 2 per thread
    int c0 = tid, c1 = tid + 256;
    int r0_ = c0 >> 2, q0 = c0 & 3, r1_ = c1 >> 2, q1 = c1 & 3;

    // issue loads for chunk j into stage j%STAGES
    auto issue = [&](int j) {
        int ph = j >> 5, kk = j & 31;
        const __nv_bfloat16* Ab = (ph == 1 ? Alo : Ahi) + (size_t)bm * DIM + kk * 32;
        const __nv_bfloat16* Bb = (ph == 2 ? Blo : Bhi) + (size_t)bn * DIM + kk * 32;
        uint32_t st = dsm + (j & (STAGES - 1)) * STAGE_BYTES;
        cp_async16(st + r0_ * A_STRIDE + q0 * 16, Ab + (size_t)r0_ * DIM + q0 * 8);
        cp_async16(st + r1_ * A_STRIDE + q1 * 16, Ab + (size_t)r1_ * DIM + q1 * 8);
        cp_async16(st + TILE_A_BYTES + r0_ * A_STRIDE + q0 * 16, Bb + (size_t)r0_ * DIM + q0 * 8);
        cp_async16(st + TILE_A_BYTES + r1_ * A_STRIDE + q1 * 16, Bb + (size_t)r1_ * DIM + q1 * 8);
        cp_commit();
    };

    #pragma unroll
    for (int j = 0; j < STAGES - 1; ++j) issue(j);

    // ldmatrix lane addressing (fixed per thread)
    int t8 = lid >> 3, l8 = lid & 7;
    uint32_t a_lane = (uint32_t)((wm * 64 + (t8 & 1) * 8 + l8) * A_STRIDE + (t8 >> 1) * 16);
    uint32_t b_lane = (uint32_t)((wn * 32 + (t8 >> 1) * 8 + l8) * A_STRIDE + (t8 & 1) * 16);

    for (int j = 0; j < CHUNKS; ++j) {
        CP_WAIT(STAGES - 2);
        __syncthreads();
        if (j + STAGES - 1 < CHUNKS) issue(j + STAGES - 1);

        uint32_t ab = dsm + (j & (STAGES - 1)) * STAGE_BYTES;
        uint32_t bb = ab + TILE_A_BYTES;
        #pragma unroll
        for (int ks = 0; ks < 2; ++ks) {
            uint32_t a[4][4], b[2][4];
            #pragma unroll
            for (int am = 0; am < 4; ++am)
                ldsm4(ab + a_lane + am * 16 * A_STRIDE + ks * 32,
                      a[am][0], a[am][1], a[am][2], a[am][3]);
            #pragma unroll
            for (int np = 0; np < 2; ++np)
                ldsm4(bb + b_lane + np * 16 * A_STRIDE + ks * 32,
                      b[np][0], b[np][1], b[np][2], b[np][3]);
            #pragma unroll
            for (int am = 0; am < 4; ++am)
                #pragma unroll
                for (int an = 0; an < 4; ++an)
                    mma_bf16(acc[am][an][0], acc[am][an][1], acc[am][an][2], acc[am][an][3],
                             a[am][0], a[am][1], a[am][2], a[am][3],
                             b[an >> 1][(an & 1) * 2], b[an >> 1][(an & 1) * 2 + 1]);
        }
    }

    // ---- epilogue: bias + SiLU + (split-store or fp32 store) ----
    int er = lid >> 2, ec = (lid & 3) * 2;
    #pragma unroll
    for (int an = 0; an < 4; ++an) {
        int col = bn + wn * 32 + an * 8 + ec;
        float2 bv = bias ? *(const float2*)(bias + col) : make_float2(0.f, 0.f);
        #pragma unroll
        for (int am = 0; am < 4; ++am) {
            #pragma unroll
            for (int h = 0; h < 2; ++h) {
                int row = bm + wm * 64 + am * 16 + er + h * 8;
                float v0 = acc[am][an][h * 2 + 0] + bv.x;
                float v1 = acc[am][an][h * 2 + 1] + bv.y;
                if (applySilu) {
                    v0 = v0 / (1.0f + expf(-v0));
                    v1 = v1 / (1.0f + expf(-v1));
                }
                if (outF) {
                    *(float2*)(outF + (size_t)row * DIM + col) = make_float2(v0, v1);
                } else {
                    __nv_bfloat16 h0, l0, h1, l1;
                    split_bf16(v0, h0, l0);
                    split_bf16(v1, h1, l1);
                    __nv_bfloat16 hp[2] = {h0, h1}, lp[2] = {l0, l1};
                    *(uint32_t*)(outHi + (size_t)row * DIM + col) = *(uint32_t*)hp;
                    *(uint32_t*)(outLo + (size_t)row * DIM + col) = *(uint32_t*)lp;
                }
            }
        }
    }
}

// ===========================================================================
// block reduction over 256 threads
// ===========================================================================
__device__ __forceinline__ float block_reduce_sum_256(float v) {
    __shared__ float s[8];
    __syncthreads();
    int lane = threadIdx.x & 31, w = threadIdx.x >> 5;
    #pragma unroll
    for (int o = 16; o; o >>= 1) v += __shfl_down_sync(0xffffffffu, v, o);
    if (lane == 0) s[w] = v;
    __syncthreads();
    if (threadIdx.x == 0) {
        float t = 0.f;
        #pragma unroll
        for (int i = 0; i < 8; ++i) t += s[i];
        s[0] = t;
    }
    __syncthreads();
    return s[0];
}

// ===========================================================================
// he = logmap0(expmap0(x)); hi/lo in -> hi/lo out
// ===========================================================================
__global__ void he_kernel(const __nv_bfloat16* __restrict__ ihi,
                          const __nv_bfloat16* __restrict__ ilo,
                          __nv_bfloat16* __restrict__ ohi,
                          __nv_bfloat16* __restrict__ olo) {
    size_t base = (size_t)blockIdx.x * DIM + threadIdx.x * 4;
    uint2 hw = *(const uint2*)(ihi + base);
    uint2 lw = *(const uint2*)(ilo + base);
    __nv_bfloat16 hb[4], lb[4];
    *(uint2*)hb = hw; *(uint2*)lb = lw;
    float v[4];
    float ss = 0.f;
    #pragma unroll
    for (int q = 0; q < 4; ++q) {
        v[q] = __bfloat162float(hb[q]) + __bfloat162float(lb[q]);
        ss += v[q] * v[q];
    }
    float sum = block_reduce_sum_256(ss);
    float n = fmaxf(sqrtf(sum), EPSF);
    float sc = atanhf(fminf(tanhf(n), MAXNORM)) / n;
    #pragma unroll
    for (int q = 0; q < 4; ++q) split_bf16(sc * v[q], hb[q], lb[q]);
    *(uint2*)(ohi + base) = *(uint2*)hb;
    *(uint2*)(olo + base) = *(uint2*)lb;
}

// ===========================================================================
// agg[b,c,d] = sum_r (edge[b,r,c]!=0) * m[b,r,d] + bias[d]; in-place over m
// ===========================================================================
__global__ __launch_bounds__(128) void agg_kernel(float* __restrict__ m,
                                                  const int* __restrict__ edge,
                                                  const float* __restrict__ bias) {
    __shared__ float msm[SEQ * 128];
    __shared__ unsigned char adj[SEQ * 80];

    int b = blockIdx.x;
    int d0 = blockIdx.y * 128;
    int tid = threadIdx.x;

    float* mb = m + (size_t)b * SEQ * DIM + d0;
    for (int r = 0; r < SEQ; ++r)
        msm[r * 128 + tid] = mb[(size_t)r * DIM + tid];

    const int* eb = edge + (size_t)b * SEQ * SEQ;
    for (int i = tid; i < SEQ * SEQ; i += 128)
        adj[(i / SEQ) * 80 + (i % SEQ)] = (unsigned char)(eb[i] != 0);
    __syncthreads();

    float bd = bias[d0 + tid];
    for (int c = 0; c < SEQ; ++c) {
        float acc = bd;
        #pragma unroll 7
        for (int r = 0; r < SEQ; ++r)
            acc += (float)adj[r * 80 + c] * msm[r * 128 + tid];
        mb[(size_t)c * DIM + tid] = acc;
    }
}

// ===========================================================================
// out = logmap0(expmap0(leaky_relu(logmap0(expmap0(agg)))))
// ===========================================================================
__global__ void final_kernel(const float* __restrict__ in, float* __restrict__ out) {
    size_t base = (size_t)blockIdx.x * DIM;
    float4 v = ((const float4*)(in + base))[threadIdx.x];
    float ss = v.x * v.x + v.y * v.y + v.z * v.z + v.w * v.w;
    float sum = block_reduce_sum_256(ss);
    float n1 = fmaxf(sqrtf(sum), EPSF);
    float sc1 = atanhf(fminf(tanhf(n1), MAXNORM)) / n1;

    float u0 = sc1 * v.x; u0 = (u0 > 0.f) ? u0 : 0.01f * u0;
    float u1 = sc1 * v.y; u1 = (u1 > 0.f) ? u1 : 0.01f * u1;
    float u2 = sc1 * v.z; u2 = (u2 > 0.f) ? u2 : 0.01f * u2;
    float u3 = sc1 * v.w; u3 = (u3 > 0.f) ? u3 : 0.01f * u3;

    float ss2 = u0 * u0 + u1 * u1 + u2 * u2 + u3 * u3;
    float sum2 = block_reduce_sum_256(ss2);
    float n2 = fmaxf(sqrtf(sum2), EPSF);
    float sc2 = atanhf(fminf(tanhf(n2), MAXNORM)) / n2;

    float4 o;
    o.x = sc2 * u0; o.y = sc2 * u1; o.z = sc2 * u2; o.w = sc2 * u3;
    ((float4*)(out + base))[threadIdx.x] = o;
}

// ===========================================================================
extern "C" void kernel_launch(void* const* d_in, const int* in_sizes, int n_in,
                              void* d_out, int out_size) {
    const void*  tokens = d_in[0];
    const int*   edge   = (const int*)d_in[1];
    const float* tok_w  = (const float*)d_in[2];
    const float* pos_w  = (const float*)d_in[3];
    const float* mlp_w  = (const float*)d_in[4];
    const float* mlp_b  = (const float*)d_in[5];
    const float* gcn_w  = (const float*)d_in[6];
    const float* gcn_b  = (const float*)d_in[7];
    float* out = (float*)d_out;

    __nv_bfloat16 *ahi, *alo, *bhi, *blo, *whi, *wlo;
    float *bufF;
    cudaGetSymbolAddress((void**)&ahi, g_ahi);
    cudaGetSymbolAddress((void**)&alo, g_alo);
    cudaGetSymbolAddress((void**)&bhi, g_bhi);
    cudaGetSymbolAddress((void**)&blo, g_blo);
    cudaGetSymbolAddress((void**)&whi, g_whi);
    cudaGetSymbolAddress((void**)&wlo, g_wlo);
    cudaGetSymbolAddress((void**)&bufF, g_bufF);

    cudaFuncSetAttribute(mma_gemm_kernel,
                         cudaFuncAttributeMaxDynamicSharedMemorySize, DSM_BYTES);

    detect_tok_kernel<<<1, 256>>>((const unsigned long long*)tokens, NROWS / 2);
    embed_kernel<<<NROWS, 256>>>(tokens, tok_w, pos_w, ahi, alo);
    wsplit_kernel<<<dim3(32, 32, 6), dim3(32, 8)>>>(mlp_w, gcn_w, whi, wlo);

    dim3 gg(NROWS / 128, DIM / 128);
    const size_t WM = (size_t)DIM * DIM;
    // project_emb: 5 linears, SiLU after first 4 (hi/lo fused split outputs)
    mma_gemm_kernel<<<gg, 256, DSM_BYTES>>>(ahi, alo, whi + 0 * WM, wlo + 0 * WM,
                                            mlp_b + 0 * DIM, bhi, blo, nullptr, 1);
    mma_gemm_kernel<<<gg, 256, DSM_BYTES>>>(bhi, blo, whi + 1 * WM, wlo + 1 * WM,
                                            mlp_b + 1 * DIM, ahi, alo, nullptr, 1);
    mma_gemm_kernel<<<gg, 256, DSM_BYTES>>>(ahi, alo, whi + 2 * WM, wlo + 2 * WM,
                                            mlp_b + 2 * DIM, bhi, blo, nullptr, 1);
    mma_gemm_kernel<<<gg, 256, DSM_BYTES>>>(bhi, blo, whi + 3 * WM, wlo + 3 * WM,
                                            mlp_b + 3 * DIM, ahi, alo, nullptr, 1);
    mma_gemm_kernel<<<gg, 256, DSM_BYTES>>>(ahi, alo, whi + 4 * WM, wlo + 4 * WM,
                                            mlp_b + 4 * DIM, bhi, blo, nullptr, 0);

    // he = logmap0(expmap0(x)) (GCN layers 0-2 are dead; only layer 3 matters)
    he_kernel<<<NROWS, 256>>>(bhi, blo, ahi, alo);

    // GCN layer 3 transform: fp32 output for aggregation
    mma_gemm_kernel<<<gg, 256, DSM_BYTES>>>(ahi, alo, whi + 5 * WM, wlo + 5 * WM,
                                            nullptr, nullptr, nullptr, bufF, 0);
    agg_kernel<<<dim3(BATCH, DIM / 128), 128>>>(bufF, edge, gcn_b + 3 * DIM);

    final_kernel<<<NROWS, 256>>>(bufF, out);
}

// round 5
// speedup vs baseline: 2.6171x; 1.2653x over previous
#include <cuda_runtime.h>
#include <cuda_bf16.h>
#include <math.h>
#include <stdint.h>

#define NROWS 19712   // 256*77
#define SEQ 77
#define BATCH 256
#define DIM 1024
#define EPSF 1e-15f
#define MAXNORM (1.0f - 1e-5f)

// scratch (no allocations allowed)
__device__ __nv_bfloat16 g_ahi[(size_t)NROWS * DIM];
__device__ __nv_bfloat16 g_alo[(size_t)NROWS * DIM];
__device__ __nv_bfloat16 g_bhi[(size_t)NROWS * DIM];
__device__ __nv_bfloat16 g_blo[(size_t)NROWS * DIM];
__device__ float g_bufF[(size_t)NROWS * DIM];
__device__ __nv_bfloat16 g_whi[(size_t)6 * DIM * DIM];  // transposed [N][K]
__device__ __nv_bfloat16 g_wlo[(size_t)6 * DIM * DIM];
__device__ int g_tok64;

// ===========================================================================
// PTX helpers (baseline sm_80+ features only — valid at compute_103)
// ===========================================================================
__device__ __forceinline__ uint32_t smem_u32(const void* p) {
    uint32_t a;
    asm("{ .reg .u64 t; cvta.to.shared.u64 t, %1; cvt.u32.u64 %0, t; }" : "=r"(a) : "l"(p));
    return a;
}
__device__ __forceinline__ void cp_async16(uint32_t dst, const void* src) {
    asm volatile("cp.async.cg.shared.global [%0], [%1], 16;" :: "r"(dst), "l"(src) : "memory");
}
__device__ __forceinline__ void cp_commit() {
    asm volatile("cp.async.commit_group;" ::: "memory");
}
#define CP_WAIT(n) asm volatile("cp.async.wait_group %0;" :: "n"(n) : "memory")

__device__ __forceinline__ void ldsm4(uint32_t addr, uint32_t& r0, uint32_t& r1,
                                      uint32_t& r2, uint32_t& r3) {
    asm volatile("ldmatrix.sync.aligned.m8n8.x4.shared.b16 {%0,%1,%2,%3}, [%4];"
                 : "=r"(r0), "=r"(r1), "=r"(r2), "=r"(r3) : "r"(addr));
}
__device__ __forceinline__ void mma_bf16(float& d0, float& d1, float& d2, float& d3,
                                         uint32_t a0, uint32_t a1, uint32_t a2, uint32_t a3,
                                         uint32_t b0, uint32_t b1) {
    asm volatile("mma.sync.aligned.m16n8k16.row.col.f32.bf16.bf16.f32 "
                 "{%0,%1,%2,%3},{%4,%5,%6,%7},{%8,%9},{%0,%1,%2,%3};"
                 : "+f"(d0), "+f"(d1), "+f"(d2), "+f"(d3)
                 : "r"(a0), "r"(a1), "r"(a2), "r"(a3), "r"(b0), "r"(b1));
}
__device__ __forceinline__ void split_bf16(float v, __nv_bfloat16& hi, __nv_bfloat16& lo) {
    hi = __float2bfloat16(v);
    lo = __float2bfloat16(v - __bfloat162float(hi));
}

// ===========================================================================
// Token layout detection (int64 vs int32 wire format)
// ===========================================================================
__global__ void detect_tok_kernel(const unsigned long long* __restrict__ w, int nwords) {
    __shared__ int flag;
    if (threadIdx.x == 0) flag = 0;
    __syncthreads();
    int bad = 0;
    for (int i = threadIdx.x; i < nwords; i += blockDim.x)
        if (w[i] >> 32) { bad = 1; break; }
    if (bad) flag = 1;
    __syncthreads();
    if (threadIdx.x == 0) g_tok64 = flag ? 0 : 1;
}

// ===========================================================================
// Embedding -> hi/lo bf16 split
// ===========================================================================
__global__ void embed_kernel(const void* __restrict__ tokens,
                             const float* __restrict__ tok_w,
                             const float* __restrict__ pos_w,
                             __nv_bfloat16* __restrict__ xhi,
                             __nv_bfloat16* __restrict__ xlo) {
    int row = blockIdx.x;
    int s = row % SEQ;
    long long t;
    if (g_tok64) t = ((const long long*)tokens)[row];
    else         t = (long long)(((const int*)tokens)[row]);
    int i = threadIdx.x;
    float4 a = ((const float4*)(tok_w + (size_t)t * DIM))[i];
    float4 p = ((const float4*)(pos_w + (size_t)s * DIM))[i];
    float v[4] = {a.x + p.x, a.y + p.y, a.z + p.z, a.w + p.w};
    __nv_bfloat16 h[4], l[4];
    #pragma unroll
    for (int q = 0; q < 4; ++q) split_bf16(v[q], h[q], l[q]);
    size_t base = (size_t)row * DIM + i * 4;
    *(uint2*)(xhi + base) = *(uint2*)h;
    *(uint2*)(xlo + base) = *(uint2*)l;
}

// ===========================================================================
// Weight transpose + split: whi/wlo[mat][n*DIM+k] = split(src[k*DIM+n])
// ===========================================================================
__global__ void wsplit_kernel(const float* __restrict__ mlp_w,
                              const float* __restrict__ gcn_w,
                              __nv_bfloat16* __restrict__ whi,
                              __nv_bfloat16* __restrict__ wlo) {
    __shared__ float t[32][33];
    int mat = blockIdx.z;
    const float* src = (mat < 5) ? mlp_w + (size_t)mat * DIM * DIM
                                 : gcn_w + (size_t)3 * DIM * DIM;
    size_t doff = (size_t)mat * DIM * DIM;
    int n0 = blockIdx.x * 32, k0 = blockIdx.y * 32;
    for (int i = threadIdx.y; i < 32; i += 8)
        t[i][threadIdx.x] = src[(size_t)(k0 + i) * DIM + n0 + threadIdx.x];
    __syncthreads();
    for (int i = threadIdx.y; i < 32; i += 8) {
        float v = t[threadIdx.x][i];
        __nv_bfloat16 h, l;
        split_bf16(v, h, l);
        size_t d = doff + (size_t)(n0 + i) * DIM + k0 + threadIdx.x;
        whi[d] = h; wlo[d] = l;
    }
}

// ===========================================================================
// bf16 3-pass GEMM via mma.sync, shared operand tiles per K-chunk.
// Per chunk (BK=32): load Ahi/Alo/Bhi/Blo tiles once, run 3 passes
// (Ah*Bh + Al*Bh + Ah*Bl) into one fp32 accumulator.
// 128x128 CTA tile, 3-stage cp.async, XOR-swizzled 64B rows, 8 warps x 64x32.
// ===========================================================================
#define STAGES 3
#define NCHUNK 32
#define TILE_BYTES 8192               // 128 rows x 64B
#define STAGE_BYTES (4 * TILE_BYTES)  // 32 KB
#define DSM_BYTES (STAGES * STAGE_BYTES)  // 96 KB

__global__ __launch_bounds__(256, 2) void mma_gemm_kernel(
    const __nv_bfloat16* __restrict__ Ahi, const __nv_bfloat16* __restrict__ Alo,
    const __nv_bfloat16* __restrict__ Bhi, const __nv_bfloat16* __restrict__ Blo,
    const float* __restrict__ bias,
    __nv_bfloat16* __restrict__ outHi, __nv_bfloat16* __restrict__ outLo,
    float* __restrict__ outF, int applySilu)
{
    extern __shared__ char dsm_raw[];
    uint32_t dsm = smem_u32(dsm_raw);

    int tid = threadIdx.x, wid = tid >> 5, lid = tid & 31;
    int bn = blockIdx.x * 128, bm = blockIdx.y * 128;   // x = n (8) for L2 reuse
    int wm = wid & 1, wn = wid >> 1;   // warp tile: rows wm*64, cols wn*32

    float acc[4][4][4];
    #pragma unroll
    for (int i = 0; i < 4; ++i)
        #pragma unroll
        for (int j = 0; j < 4; ++j)
            #pragma unroll
            for (int r = 0; r < 4; ++r) acc[i][j][r] = 0.f;

    // cp.async: 2048 16B-chunks per stage, 8 per thread.
    // chunk i: tile t=i>>9 (0=Ah,1=Al,2=Bh,3=Bl), row r=(i>>2)&127, col c=i&3
    // smem addr = stage + t*8192 + r*64 + ((c ^ ((r>>1)&3)) * 16)
    auto issue = [&](int j) {
        int k0 = j * 32;
        uint32_t st = dsm + (j % STAGES) * STAGE_BYTES;
        #pragma unroll
        for (int u = 0; u < 8; ++u) {
            int i = tid + u * 256;
            int t = i >> 9, r = (i >> 2) & 127, c = i & 3;
            const __nv_bfloat16* gb;
            if (t == 0)      gb = Ahi + (size_t)(bm + r) * DIM;
            else if (t == 1) gb = Alo + (size_t)(bm + r) * DIM;
            else if (t == 2) gb = Bhi + (size_t)(bn + r) * DIM;
            else             gb = Blo + (size_t)(bn + r) * DIM;
            uint32_t daddr = st + t * TILE_BYTES + r * 64 + (((c ^ ((r >> 1) & 3))) * 16);
            cp_async16(daddr, gb + k0 + c * 8);
        }
        cp_commit();
    };

    issue(0); issue(1);

    // ldmatrix lane addressing: swizzle term is (l8>>1)&3, constant per lane
    int t8 = lid >> 3, l8 = lid & 7;
    uint32_t sw = (uint32_t)((l8 >> 1) & 3);
    uint32_t a_row = (uint32_t)(wm * 64 + (t8 & 1) * 8 + l8);
    uint32_t b_row = (uint32_t)(wn * 32 + (t8 >> 1) * 8 + l8);
    uint32_t a_c = (uint32_t)(t8 >> 1);       // 16B col 0/1, +ks*2
    uint32_t b_c = (uint32_t)(t8 & 1);

    for (int j = 0; j < NCHUNK; ++j) {
        CP_WAIT(1);
        __syncthreads();
        if (j + 2 < NCHUNK) issue(j + 2);

        uint32_t st = dsm + (j % STAGES) * STAGE_BYTES;
        #pragma unroll
        for (int ks = 0; ks < 2; ++ks) {
            uint32_t a_off = ((a_c + ks * 2) ^ sw) * 16;
            uint32_t b_off = ((b_c + ks * 2) ^ sw) * 16;
            uint32_t ah[4][4], al[4][4], bh[2][4], bl[2][4];
            #pragma unroll
            for (int am = 0; am < 4; ++am) {
                uint32_t ra = st + (a_row + am * 16) * 64 + a_off;
                ldsm4(ra, ah[am][0], ah[am][1], ah[am][2], ah[am][3]);
                ldsm4(ra + TILE_BYTES, al[am][0], al[am][1], al[am][2], al[am][3]);
            }
            #pragma unroll
            for (int np = 0; np < 2; ++np) {
                uint32_t rb = st + 2 * TILE_BYTES + (b_row + np * 16) * 64 + b_off;
                ldsm4(rb, bh[np][0], bh[np][1], bh[np][2], bh[np][3]);
                ldsm4(rb + TILE_BYTES, bl[np][0], bl[np][1], bl[np][2], bl[np][3]);
            }
            #pragma unroll
            for (int am = 0; am < 4; ++am)
                #pragma unroll
                for (int an = 0; an < 4; ++an) {
                    uint32_t* bp = bh[an >> 1];
                    mma_bf16(acc[am][an][0], acc[am][an][1], acc[am][an][2], acc[am][an][3],
                             ah[am][0], ah[am][1], ah[am][2], ah[am][3],
                             bp[(an & 1) * 2], bp[(an & 1) * 2 + 1]);
                }
            #pragma unroll
            for (int am = 0; am < 4; ++am)
                #pragma unroll
                for (int an = 0; an < 4; ++an) {
                    uint32_t* bp = bh[an >> 1];
                    mma_bf16(acc[am][an][0], acc[am][an][1], acc[am][an][2], acc[am][an][3],
                             al[am][0], al[am][1], al[am][2], al[am][3],
                             bp[(an & 1) * 2], bp[(an & 1) * 2 + 1]);
                }
            #pragma unroll
            for (int am = 0; am < 4; ++am)
                #pragma unroll
                for (int an = 0; an < 4; ++an) {
                    uint32_t* bp = bl[an >> 1];
                    mma_bf16(acc[am][an][0], acc[am][an][1], acc[am][an][2], acc[am][an][3],
                             ah[am][0], ah[am][1], ah[am][2], ah[am][3],
                             bp[(an & 1) * 2], bp[(an & 1) * 2 + 1]);
                }
        }
    }

    // ---- epilogue: bias + SiLU + (split-store or fp32 store) ----
    int er = lid >> 2, ec = (lid & 3) * 2;
    #pragma unroll
    for (int an = 0; an < 4; ++an) {
        int col = bn + wn * 32 + an * 8 + ec;
        float2 bv = bias ? *(const float2*)(bias + col) : make_float2(0.f, 0.f);
        #pragma unroll
        for (int am = 0; am < 4; ++am) {
            #pragma unroll
            for (int h = 0; h < 2; ++h) {
                int row = bm + wm * 64 + am * 16 + er + h * 8;
                float v0 = acc[am][an][h * 2 + 0] + bv.x;
                float v1 = acc[am][an][h * 2 + 1] + bv.y;
                if (applySilu) {
                    v0 = v0 / (1.0f + expf(-v0));
                    v1 = v1 / (1.0f + expf(-v1));
                }
                if (outF) {
                    *(float2*)(outF + (size_t)row * DIM + col) = make_float2(v0, v1);
                } else {
                    __nv_bfloat16 h0, l0, h1, l1;
                    split_bf16(v0, h0, l0);
                    split_bf16(v1, h1, l1);
                    __nv_bfloat16 hp[2] = {h0, h1}, lp[2] = {l0, l1};
                    *(uint32_t*)(outHi + (size_t)row * DIM + col) = *(uint32_t*)hp;
                    *(uint32_t*)(outLo + (size_t)row * DIM + col) = *(uint32_t*)lp;
                }
            }
        }
    }
}

// ===========================================================================
// block reduction over 256 threads
// ===========================================================================
__device__ __forceinline__ float block_reduce_sum_256(float v) {
    __shared__ float s[8];
    __syncthreads();
    int lane = threadIdx.x & 31, w = threadIdx.x >> 5;
    #pragma unroll
    for (int o = 16; o; o >>= 1) v += __shfl_down_sync(0xffffffffu, v, o);
    if (lane == 0) s[w] = v;
    __syncthreads();
    if (threadIdx.x == 0) {
        float t = 0.f;
        #pragma unroll
        for (int i = 0; i < 8; ++i) t += s[i];
        s[0] = t;
    }
    __syncthreads();
    return s[0];
}

// ===========================================================================
// he = logmap0(expmap0(x)); hi/lo in -> hi/lo out
// ===========================================================================
__global__ void he_kernel(const __nv_bfloat16* __restrict__ ihi,
                          const __nv_bfloat16* __restrict__ ilo,
                          __nv_bfloat16* __restrict__ ohi,
                          __nv_bfloat16* __restrict__ olo) {
    size_t base = (size_t)blockIdx.x * DIM + threadIdx.x * 4;
    uint2 hw = *(const uint2*)(ihi + base);
    uint2 lw = *(const uint2*)(ilo + base);
    __nv_bfloat16 hb[4], lb[4];
    *(uint2*)hb = hw; *(uint2*)lb = lw;
    float v[4];
    float ss = 0.f;
    #pragma unroll
    for (int q = 0; q < 4; ++q) {
        v[q] = __bfloat162float(hb[q]) + __bfloat162float(lb[q]);
        ss += v[q] * v[q];
    }
    float sum = block_reduce_sum_256(ss);
    float n = fmaxf(sqrtf(sum), EPSF);
    float sc = atanhf(fminf(tanhf(n), MAXNORM)) / n;
    #pragma unroll
    for (int q = 0; q < 4; ++q) split_bf16(sc * v[q], hb[q], lb[q]);
    *(uint2*)(ohi + base) = *(uint2*)hb;
    *(uint2*)(olo + base) = *(uint2*)lb;
}

// ===========================================================================
// agg[b,c,d] = sum_r (edge[b,r,c]!=0) * m[b,r,d] + bias[d]; in-place over m
// ===========================================================================
__global__ __launch_bounds__(128) void agg_kernel(float* __restrict__ m,
                                                  const int* __restrict__ edge,
                                                  const float* __restrict__ bias) {
    __shared__ float msm[SEQ * 128];
    __shared__ unsigned char adj[SEQ * 80];

    int b = blockIdx.x;
    int d0 = blockIdx.y * 128;
    int tid = threadIdx.x;

    float* mb = m + (size_t)b * SEQ * DIM + d0;
    for (int r = 0; r < SEQ; ++r)
        msm[r * 128 + tid] = mb[(size_t)r * DIM + tid];

    const int* eb = edge + (size_t)b * SEQ * SEQ;
    for (int i = tid; i < SEQ * SEQ; i += 128)
        adj[(i / SEQ) * 80 + (i % SEQ)] = (unsigned char)(eb[i] != 0);
    __syncthreads();

    float bd = bias[d0 + tid];
    for (int c = 0; c < SEQ; ++c) {
        float acc = bd;
        #pragma unroll 7
        for (int r = 0; r < SEQ; ++r)
            acc += (float)adj[r * 80 + c] * msm[r * 128 + tid];
        mb[(size_t)c * DIM + tid] = acc;
    }
}

// ===========================================================================
// out = logmap0(expmap0(leaky_relu(logmap0(expmap0(agg)))))
// ===========================================================================
__global__ void final_kernel(const float* __restrict__ in, float* __restrict__ out) {
    size_t base = (size_t)blockIdx.x * DIM;
    float4 v = ((const float4*)(in + base))[threadIdx.x];
    float ss = v.x * v.x + v.y * v.y + v.z * v.z + v.w * v.w;
    float sum = block_reduce_sum_256(ss);
    float n1 = fmaxf(sqrtf(sum), EPSF);
    float sc1 = atanhf(fminf(tanhf(n1), MAXNORM)) / n1;

    float u0 = sc1 * v.x; u0 = (u0 > 0.f) ? u0 : 0.01f * u0;
    float u1 = sc1 * v.y; u1 = (u1 > 0.f) ? u1 : 0.01f * u1;
    float u2 = sc1 * v.z; u2 = (u2 > 0.f) ? u2 : 0.01f * u2;
    float u3 = sc1 * v.w; u3 = (u3 > 0.f) ? u3 : 0.01f * u3;

    float ss2 = u0 * u0 + u1 * u1 + u2 * u2 + u3 * u3;
    float sum2 = block_reduce_sum_256(ss2);
    float n2 = fmaxf(sqrtf(sum2), EPSF);
    float sc2 = atanhf(fminf(tanhf(n2), MAXNORM)) / n2;

    float4 o;
    o.x = sc2 * u0; o.y = sc2 * u1; o.z = sc2 * u2; o.w = sc2 * u3;
    ((float4*)(out + base))[threadIdx.x] = o;
}

// ===========================================================================
extern "C" void kernel_launch(void* const* d_in, const int* in_sizes, int n_in,
                              void* d_out, int out_size) {
    const void*  tokens = d_in[0];
    const int*   edge   = (const int*)d_in[1];
    const float* tok_w  = (const float*)d_in[2];
    const float* pos_w  = (const float*)d_in[3];
    const float* mlp_w  = (const float*)d_in[4];
    const float* mlp_b  = (const float*)d_in[5];
    const float* gcn_w  = (const float*)d_in[6];
    const float* gcn_b  = (const float*)d_in[7];
    float* out = (float*)d_out;

    __nv_bfloat16 *ahi, *alo, *bhi, *blo, *whi, *wlo;
    float *bufF;
    cudaGetSymbolAddress((void**)&ahi, g_ahi);
    cudaGetSymbolAddress((void**)&alo, g_alo);
    cudaGetSymbolAddress((void**)&bhi, g_bhi);
    cudaGetSymbolAddress((void**)&blo, g_blo);
    cudaGetSymbolAddress((void**)&whi, g_whi);
    cudaGetSymbolAddress((void**)&wlo, g_wlo);
    cudaGetSymbolAddress((void**)&bufF, g_bufF);

    cudaFuncSetAttribute(mma_gemm_kernel,
                         cudaFuncAttributeMaxDynamicSharedMemorySize, DSM_BYTES);

    detect_tok_kernel<<<1, 256>>>((const unsigned long long*)tokens, NROWS / 2);
    embed_kernel<<<NROWS, 256>>>(tokens, tok_w, pos_w, ahi, alo);
    wsplit_kernel<<<dim3(32, 32, 6), dim3(32, 8)>>>(mlp_w, gcn_w, whi, wlo);

    dim3 gg(DIM / 128, NROWS / 128);   // x = n (fast) for cross-CTA L2 reuse
    const size_t WM = (size_t)DIM * DIM;
    // project_emb: 5 linears, SiLU after first 4 (hi/lo fused split outputs)
    mma_gemm_kernel<<<gg, 256, DSM_BYTES>>>(ahi, alo, whi + 0 * WM, wlo + 0 * WM,
                                            mlp_b + 0 * DIM, bhi, blo, nullptr, 1);
    mma_gemm_kernel<<<gg, 256, DSM_BYTES>>>(bhi, blo, whi + 1 * WM, wlo + 1 * WM,
                                            mlp_b + 1 * DIM, ahi, alo, nullptr, 1);
    mma_gemm_kernel<<<gg, 256, DSM_BYTES>>>(ahi, alo, whi + 2 * WM, wlo + 2 * WM,
                                            mlp_b + 2 * DIM, bhi, blo, nullptr, 1);
    mma_gemm_kernel<<<gg, 256, DSM_BYTES>>>(bhi, blo, whi + 3 * WM, wlo + 3 * WM,
                                            mlp_b + 3 * DIM, ahi, alo, nullptr, 1);
    mma_gemm_kernel<<<gg, 256, DSM_BYTES>>>(ahi, alo, whi + 4 * WM, wlo + 4 * WM,
                                            mlp_b + 4 * DIM, bhi, blo, nullptr, 0);

    // he = logmap0(expmap0(x)) (GCN layers 0-2 are dead; only layer 3 matters)
    he_kernel<<<NROWS, 256>>>(bhi, blo, ahi, alo);

    // GCN layer 3 transform: fp32 output for aggregation
    mma_gemm_kernel<<<gg, 256, DSM_BYTES>>>(ahi, alo, whi + 5 * WM, wlo + 5 * WM,
                                            nullptr, nullptr, nullptr, bufF, 0);
    agg_kernel<<<dim3(BATCH, DIM / 128), 128>>>(bufF, edge, gcn_b + 3 * DIM);

    final_kernel<<<NROWS, 256>>>(bufF, out);
}